// round 15
// baseline (speedup 1.0000x reference)
#include <cuda_runtime.h>
#include <cuda_fp16.h>
#include <math.h>

#define NN 100000
#define NNP 100096      // 782 * 128
#define NE 800000
#define NG 2048
#define NB 196
#define CAP 160

typedef unsigned int uint;

// ---------------- scratch (device globals; no runtime allocation) ----------------
__device__ __half g_hh[NN*64];              // node features fp16 (ping)
__device__ __half g_hh2[NN*64];             // node features fp16 (pong)
__device__ __half g_Af[(size_t)NNP*320];    // fp16 aggregation panel (pad rows stay zero)
__device__ __half g_Bfh[64*384];            // B^T fp16: [n][k]
__device__ int   g_cnt[NN];
__device__ int   g_rowptr[NN+1];
__device__ int   g_bsum[NB];
__device__ int   g_fill[NN];
__device__ int   g_eidx[NE];                // packed: src | (rel<<20)
__device__ int   g_gstart[NG+1];
__device__ float g_Wl[192*256];
__device__ float g_bl[256];
__device__ float g_s2s[NG*256];             // qstar | hx | cx
__device__ float g_gates[NG*256];

#define G_QS (g_s2s)
#define G_HX (g_s2s + NG*128)
#define G_CX (g_s2s + NG*192)

// ---------------- prep kernels ----------------
__global__ void k_wc(const float* __restrict__ att, const float* __restrict__ basis,
                     const float* __restrict__ root){
  int k = blockIdx.x, e = threadIdx.x;
  float s;
  if (k < 320){
    int r = k >> 6, d = k & 63;
    s = 0.f;
    #pragma unroll
    for (int b = 0; b < 5; b++) s += att[r*5+b] * basis[(b*64+d)*64+e];
  } else {
    s = root[(k-320)*64 + e];
  }
  g_Bfh[e*384 + k] = __float2half_rn(s);
}

// h0 + zero g_cnt (runs before k_hist)
__global__ void __launch_bounds__(256) k_h0(const float* __restrict__ x,
                                            const float* __restrict__ w,
                                            const float* __restrict__ b){
  int gid = blockIdx.x*256 + threadIdx.x;
  if (gid < NN) g_cnt[gid] = 0;
  __shared__ float sx[4][15];
  int tid = threadIdx.x;
  int local = tid >> 6, e = tid & 63;
  int n = blockIdx.x*4 + local;
  if (e < 15 && n < NN) sx[local][e] = x[n*15+e];
  __syncthreads();
  if (n >= NN) return;
  float s = b[e];
  #pragma unroll
  for (int i = 0; i < 15; i++) s += sx[local][i]*w[i*64+e];
  g_hh[(size_t)n*64+e] = __float2half_rn(fmaxf(s, 0.f));
}

__global__ void k_hist(const int* __restrict__ dst){
  int e = blockIdx.x*blockDim.x + threadIdx.x;
  if (e < NE) atomicAdd(&g_cnt[dst[e]], 1);
}

__global__ void k_scan1(){
  __shared__ int sm[512];
  int b = blockIdx.x, t = threadIdx.x;
  int i = b*512 + t;
  sm[t] = (i < NN) ? g_cnt[i] : 0;
  __syncthreads();
  for (int o = 256; o; o >>= 1){
    if (t < o) sm[t] += sm[t+o];
    __syncthreads();
  }
  if (t == 0) g_bsum[b] = sm[0];
}

// merged scan2+scan3 + zero g_fill
__global__ void k_scan23(){
  __shared__ int sm[512];
  __shared__ int sb[256];
  int b = blockIdx.x, t = threadIdx.x;
  if (t < 256) sb[t] = (t < NB) ? g_bsum[t] : 0;
  __syncthreads();
  for (int o = 1; o < 256; o <<= 1){
    int a = (t < 256 && t >= o) ? sb[t-o] : 0;
    __syncthreads();
    if (t < 256) sb[t] += a;
    __syncthreads();
  }
  int off = (b == 0) ? 0 : sb[b-1];
  int i = b*512 + t;
  int v = (i < NN) ? g_cnt[i] : 0;
  sm[t] = v;
  __syncthreads();
  for (int o = 1; o < 512; o <<= 1){
    int add = (t >= o) ? sm[t-o] : 0;
    __syncthreads();
    sm[t] += add;
    __syncthreads();
  }
  if (i < NN){
    g_rowptr[i] = off + sm[t] - v;
    g_fill[i] = 0;
  }
  if (b == 0 && t == 0) g_rowptr[NN] = NE;
}

__global__ void k_scatter(const int* __restrict__ ei, const int* __restrict__ et){
  int e = blockIdx.x*blockDim.x + threadIdx.x;
  if (e >= NE) return;
  int src = ei[e];
  int dst = ei[NE + e];
  int rel = et[e];
  int pos = g_rowptr[dst] + atomicAdd(&g_fill[dst], 1);
  g_eidx[pos] = src | (rel << 20);
}

// LSTM weight pack + graph-offset binary search + s2s state zero
__global__ void k_wl(const float* __restrict__ w_ih, const float* __restrict__ w_hh,
                     const float* __restrict__ b_ih, const float* __restrict__ b_hh,
                     const int* __restrict__ batch){
  int k = blockIdx.x, j = threadIdx.x;
  g_Wl[k*256+j] = (k < 128) ? w_ih[j*128+k] : w_hh[j*64 + (k-128)];
  if (k == 0) g_bl[j] = b_ih[j] + b_hh[j];
  int gt = blockIdx.x*256 + threadIdx.x;
  for (int i = gt; i < NG*256; i += 192*256) g_s2s[i] = 0.f;
  if (gt <= NG){
    int lo = 0, hi = NN;
    while (lo < hi){ int mid = (lo+hi) >> 1; if (batch[mid] < gt) lo = mid+1; else hi = mid; }
    g_gstart[gt] = lo;
  }
}

// ---------------- aggregation: warp-per-node CSR over fp16 h -> fp16 panel ----------------
__global__ void __launch_bounds__(256) k_agg(const __half* __restrict__ hin){
  int n = (blockIdx.x*blockDim.x + threadIdx.x) >> 5;
  int lane = threadIdx.x & 31;
  float ac[5][2] = {};
  int rp0 = g_rowptr[n], rp1 = g_rowptr[n+1];
  int e = rp0;
  for (; e + 2 <= rp1; e += 2){
    int p0 = g_eidx[e], p1 = g_eidx[e+1];
    float2 x = __half22float2(*(const __half2*)(hin + (size_t)(p0 & 0xFFFFF)*64 + 2*lane));
    float2 y = __half22float2(*(const __half2*)(hin + (size_t)(p1 & 0xFFFFF)*64 + 2*lane));
    int r0 = p0 >> 20, r1 = p1 >> 20;
    #pragma unroll
    for (int r = 0; r < 5; r++){
      if (r0 == r){ ac[r][0] += x.x; ac[r][1] += x.y; }
      if (r1 == r){ ac[r][0] += y.x; ac[r][1] += y.y; }
    }
  }
  if (e < rp1){
    int p0 = g_eidx[e];
    float2 x = __half22float2(*(const __half2*)(hin + (size_t)(p0 & 0xFFFFF)*64 + 2*lane));
    int r0 = p0 >> 20;
    #pragma unroll
    for (int r = 0; r < 5; r++)
      if (r0 == r){ ac[r][0] += x.x; ac[r][1] += x.y; }
  }
  float ic = 1.0f / fmaxf((float)(rp1 - rp0), 1.0f);
  size_t base = (size_t)n*320 + 2*lane;
  #pragma unroll
  for (int r = 0; r < 5; r++){
    float2 v = { ac[r][0]*ic, ac[r][1]*ic };
    *(__half2*)(g_Af + base + r*64) = __float22half2_rn(v);
  }
}

// ---------------- GEMM: [NNP x 384] @ [384 x 64] fp16 MMA, 1-term, double-buffered ----------------
#define MMA_F16(d, a, b0v, b1v) \
  asm volatile("mma.sync.aligned.m16n8k16.row.col.f32.f16.f16.f32 " \
      "{%0,%1,%2,%3}, {%4,%5,%6,%7}, {%8,%9}, {%0,%1,%2,%3};" \
      : "+f"(d[0]), "+f"(d[1]), "+f"(d[2]), "+f"(d[3]) \
      : "r"(a[0]), "r"(a[1]), "r"(a[2]), "r"(a[3]), "r"(b0v), "r"(b1v))

__global__ void __launch_bounds__(256) k_gemm(const __half* __restrict__ hin,
                                              __half* __restrict__ hout,
                                              const float* __restrict__ cb){
  __shared__ __half Ah_s[2][128][40];
  __shared__ __half Bh_s[2][64][40];
  int tid = threadIdx.x, lane = tid & 31, w = tid >> 5;
  int m0 = blockIdx.x * 128;
  int wrow = w * 16;
  int r = lane >> 2;            // 0..7
  int q2 = (lane & 3) * 2;      // 0,2,4,6

  float acc[8][4];
  #pragma unroll
  for (int nt = 0; nt < 8; nt++)
    #pragma unroll
    for (int j = 0; j < 4; j++) acc[nt][j] = 0.f;

  int srow = tid >> 1, sseg = (tid & 1) * 16;    // A staging: 16 halves per thread
  int sn = tid >> 2,  sbs = (tid & 3) * 8;       // B staging: 8 halves per thread
  int rw = m0 + srow; if (rw >= NN) rw = NN - 1;
  const __half* hrow = hin + (size_t)rw*64;

  uint4 pf0, pf1, pf2;
  auto LD = [&](int cc){
    const __half* pa = (cc < 10)
        ? g_Af + (size_t)(m0 + srow)*320 + cc*32 + sseg
        : hrow + (cc - 10)*32 + sseg;
    pf0 = *(const uint4*)pa;
    pf1 = *(const uint4*)(pa + 8);
    pf2 = *(const uint4*)(g_Bfh + sn*384 + cc*32 + sbs);
  };
  auto ST = [&](int buf){
    *(uint4*)&Ah_s[buf][srow][sseg]     = pf0;
    *(uint4*)&Ah_s[buf][srow][sseg + 8] = pf1;
    *(uint4*)&Bh_s[buf][sn][sbs] = pf2;
  };

  LD(0); ST(0);
  __syncthreads();

  for (int cc = 0; cc < 12; cc++){
    int buf = cc & 1;
    if (cc < 11) LD(cc + 1);            // global loads in flight during MMA
    #pragma unroll
    for (int s = 0; s < 2; s++){
      int ks = s * 16;
      uint ah[4];
      ah[0] = *(const uint*)&Ah_s[buf][wrow + r    ][ks + q2];
      ah[1] = *(const uint*)&Ah_s[buf][wrow + r + 8][ks + q2];
      ah[2] = *(const uint*)&Ah_s[buf][wrow + r    ][ks + q2 + 8];
      ah[3] = *(const uint*)&Ah_s[buf][wrow + r + 8][ks + q2 + 8];
      #pragma unroll
      for (int nt = 0; nt < 8; nt++){
        int nn = nt*8 + r;
        uint bh0 = *(const uint*)&Bh_s[buf][nn][ks + q2];
        uint bh1 = *(const uint*)&Bh_s[buf][nn][ks + q2 + 8];
        MMA_F16(acc[nt], ah, bh0, bh1);
      }
    }
    if (cc < 11) ST(buf ^ 1);           // write other buffer (readers synced last iter)
    __syncthreads();
  }

  // epilogue: relu(acc + bias) -> fp16 h
  int row0 = m0 + wrow + r;
  #pragma unroll
  for (int nt = 0; nt < 8; nt++){
    int col = nt*8 + q2;
    float b0v = cb[col], b1v = cb[col+1];
    if (row0 < NN){
      *(__half2*)(hout + (size_t)row0*64 + col) =
        __floats2half2_rn(fmaxf(acc[nt][0] + b0v, 0.f), fmaxf(acc[nt][1] + b1v, 0.f));
    }
    if (row0 + 8 < NN){
      *(__half2*)(hout + (size_t)(row0+8)*64 + col) =
        __floats2half2_rn(fmaxf(acc[nt][2] + b0v, 0.f), fmaxf(acc[nt][3] + b1v, 0.f));
    }
  }
}

// ---------------- Set2Set ----------------
__global__ void __launch_bounds__(256) k_gates(){
  __shared__ float Asg[64][36];
  __shared__ float Bsg[32][64];
  int tid = threadIdx.x;
  int tx = tid & 15, ty = tid >> 4;
  int m0 = blockIdx.x * 64;
  int n0 = blockIdx.y * 64;
  int lrow = tid >> 2;
  int lk = (tid & 3) * 8;
  int grow = m0 + lrow;
  int bk = tid >> 3, be = (tid & 7) * 8;
  float acc[4][4] = {};
  for (int kk = 0; kk < 6; kk++){
    int kb = kk * 32;
    float4 a0, a1;
    if (kk < 4){
      const float* p = G_QS + grow*128 + kb + lk;
      a0 = *(const float4*)p; a1 = *(const float4*)(p+4);
    } else {
      const float* p = G_HX + grow*64 + (kb - 128) + lk;
      a0 = *(const float4*)p; a1 = *(const float4*)(p+4);
    }
    const float* wp = g_Wl + (kb + bk)*256 + n0 + be;
    float4 b0 = *(const float4*)wp;
    float4 b1 = *(const float4*)(wp+4);
    __syncthreads();
    *(float4*)&Asg[lrow][lk]   = a0;
    *(float4*)&Asg[lrow][lk+4] = a1;
    *(float4*)&Bsg[bk][be]     = b0;
    *(float4*)&Bsg[bk][be+4]   = b1;
    __syncthreads();
    #pragma unroll
    for (int k = 0; k < 32; k++){
      float4 bv = *(float4*)&Bsg[k][tx*4];
      #pragma unroll
      for (int i = 0; i < 4; i++){
        float av = Asg[ty*4+i][k];
        acc[i][0] += av*bv.x;
        acc[i][1] += av*bv.y;
        acc[i][2] += av*bv.z;
        acc[i][3] += av*bv.w;
      }
    }
  }
  #pragma unroll
  for (int i = 0; i < 4; i++){
    int m = m0 + ty*4 + i;
    float* op = g_gates + m*256 + n0 + tx*4;
    op[0] = acc[i][0] + g_bl[n0 + tx*4 + 0];
    op[1] = acc[i][1] + g_bl[n0 + tx*4 + 1];
    op[2] = acc[i][2] + g_bl[n0 + tx*4 + 2];
    op[3] = acc[i][3] + g_bl[n0 + tx*4 + 3];
  }
}

__device__ __forceinline__ float sigf(float v){ return 1.0f/(1.0f + __expf(-v)); }

// fused LSTM update + softmax readout over fp16 h. Block per graph, 128 threads.
// weighted sum parallelized across 4 warps.
__global__ void __launch_bounds__(128) k_read(const __half* __restrict__ h){
  __shared__ float se[CAP];
  __shared__ float shx[64];
  __shared__ float red[1];
  __shared__ float ps[4];
  __shared__ float2 sr[4][32];
  int g = blockIdx.x;
  int tid = threadIdx.x, lane = tid & 31, w = tid >> 5;
  int s0 = g_gstart[g];
  int cnt = g_gstart[g+1] - s0;
  if (cnt > CAP) cnt = CAP;
  // LSTM update (threads 0..63)
  if (tid < 64){
    const float* ga = g_gates + g*256;
    float iv = sigf(ga[tid]);
    float fv = sigf(ga[64+tid]);
    float gv = tanhf(ga[128+tid]);
    float ov = sigf(ga[192+tid]);
    float c = fv * G_CX[g*64+tid] + iv * gv;
    float hx = ov * tanhf(c);
    G_CX[g*64+tid] = c;
    G_HX[g*64+tid] = hx;
    shx[tid] = hx;
  }
  __syncthreads();
  // e per node
  for (int i = w; i < cnt; i += 4){
    const __half2* hr = (const __half2*)(h + (size_t)(s0+i)*64);
    float2 f = __half22float2(hr[lane]);
    float s = f.x*shx[2*lane] + f.y*shx[2*lane+1];
    #pragma unroll
    for (int o = 16; o; o >>= 1) s += __shfl_xor_sync(0xffffffffu, s, o);
    if (lane == 0) se[i] = s;
  }
  __syncthreads();
  // max
  if (tid < 32){
    float m = -3.0e38f;
    for (int i = lane; i < cnt; i += 32) m = fmaxf(m, se[i]);
    #pragma unroll
    for (int o = 16; o; o >>= 1) m = fmaxf(m, __shfl_xor_sync(0xffffffffu, m, o));
    if (lane == 0) red[0] = m;
  }
  __syncthreads();
  float m = red[0];
  // exp + partial sums
  float psum = 0.f;
  for (int i = tid; i < cnt; i += 128){
    float v = __expf(se[i] - m);
    se[i] = v;
    psum += v;
  }
  #pragma unroll
  for (int o = 16; o; o >>= 1) psum += __shfl_xor_sync(0xffffffffu, psum, o);
  if (lane == 0) ps[w] = psum;
  __syncthreads();
  float ssum = ps[0] + ps[1] + ps[2] + ps[3];
  // weighted sum: warp w handles nodes i = w, w+4, ... ; lane -> dim pair
  {
    float r0 = 0.f, r1 = 0.f;
    for (int i = w; i < cnt; i += 4){
      float a = se[i];
      const __half2* hr = (const __half2*)(h + (size_t)(s0+i)*64);
      float2 f = __half22float2(hr[lane]);
      r0 += a * f.x;
      r1 += a * f.y;
    }
    sr[w][lane] = make_float2(r0, r1);
  }
  __syncthreads();
  if (tid < 64){
    int pair = tid >> 1, comp = tid & 1;
    float r = 0.f;
    #pragma unroll
    for (int ww = 0; ww < 4; ww++){
      float2 v = sr[ww][pair];
      r += comp ? v.y : v.x;
    }
    G_QS[g*128 + tid]      = shx[tid];
    G_QS[g*128 + 64 + tid] = (ssum > 0.f) ? (r / ssum) : 0.f;
  }
}

// ---------------- fused head ----------------
__global__ void __launch_bounds__(64) k_head(const float* __restrict__ w1,
                                             const float* __restrict__ b1,
                                             const float* __restrict__ w2,
                                             const float* __restrict__ b2,
                                             float* __restrict__ out){
  __shared__ float so[64];
  int g = blockIdx.x, e = threadIdx.x;
  const float* q = G_QS + g*128;
  float s = b1[e];
  #pragma unroll 8
  for (int k = 0; k < 128; k++) s += q[k]*w1[k*64+e];
  so[e] = fmaxf(s, 0.f);
  __syncthreads();
  if (e < 12){
    float s2 = b2[e];
    #pragma unroll 8
    for (int d = 0; d < 64; d++) s2 += so[d]*w2[d*12+e];
    out[g*12 + e] = s2;
  }
}

// ---------------- launch ----------------
extern "C" void kernel_launch(void* const* d_in, const int* in_sizes, int n_in,
                              void* d_out, int out_size){
  const float* x      = (const float*)d_in[0];
  const int*   ei     = (const int*)  d_in[1];
  const int*   et     = (const int*)  d_in[2];
  const int*   batch  = (const int*)  d_in[3];
  const float* lin0_w = (const float*)d_in[4];
  const float* lin0_b = (const float*)d_in[5];
  const float* basis  = (const float*)d_in[6];
  const float* att    = (const float*)d_in[7];
  const float* root   = (const float*)d_in[8];
  const float* conv_b = (const float*)d_in[9];
  const float* w_ih   = (const float*)d_in[10];
  const float* w_hh   = (const float*)d_in[11];
  const float* b_ih   = (const float*)d_in[12];
  const float* b_hh   = (const float*)d_in[13];
  const float* lin1_w = (const float*)d_in[14];
  const float* lin1_b = (const float*)d_in[15];
  const float* lin2_w = (const float*)d_in[16];
  const float* lin2_b = (const float*)d_in[17];
  float* out = (float*)d_out;

  void *p_h=0, *p_h2=0;
  cudaGetSymbolAddress(&p_h,  g_hh);
  cudaGetSymbolAddress(&p_h2, g_hh2);

  static cudaStream_t s1;
  static cudaEvent_t ev_fork, ev_join;
  static int sinit = 0;
  if (!sinit){
    cudaStreamCreateWithFlags(&s1, cudaStreamNonBlocking);
    cudaEventCreateWithFlags(&ev_fork, cudaEventDisableTiming);
    cudaEventCreateWithFlags(&ev_join, cudaEventDisableTiming);
    sinit = 1;
  }

  // fork: weight prep + first gates (reads only zeros) on side stream
  cudaEventRecord(ev_fork, 0);
  cudaStreamWaitEvent(s1, ev_fork, 0);
  k_wc<<<384, 64, 0, s1>>>(att, basis, root);
  k_wl<<<192, 256, 0, s1>>>(w_ih, w_hh, b_ih, b_hh, batch);
  k_gates<<<dim3(NG/64, 4), 256, 0, s1>>>();
  cudaEventRecord(ev_join, s1);

  // main chain: h0 -> CSR build -> first aggregation
  k_h0<<<(NN+3)/4, 256>>>(x, lin0_w, lin0_b);
  k_hist<<<(NE+255)/256, 256>>>(ei + NE);
  k_scan1<<<NB, 512>>>();
  k_scan23<<<NB, 512>>>();
  k_scatter<<<(NE+255)/256, 256>>>(ei, et);

  __half* hA = (__half*)p_h;
  __half* hB = (__half*)p_h2;
  k_agg<<<NN/8, 256>>>(hA);
  cudaStreamWaitEvent(0, ev_join, 0);      // need Bfh before gemm; gates0 also done
  k_gemm<<<NNP/128, 256>>>(hA, hB, conv_b);
  { __half* tmp = hA; hA = hB; hB = tmp; }
  for (int s = 1; s < 6; s++){
    k_agg<<<NN/8, 256>>>(hA);
    k_gemm<<<NNP/128, 256>>>(hA, hB, conv_b);
    __half* tmp = hA; hA = hB; hB = tmp;
  }

  // Set2Set: gates(0) already ran on s1
  k_read<<<NG, 128>>>(hA);
  for (int t = 1; t < 6; t++){
    k_gates<<<dim3(NG/64, 4), 256>>>();
    k_read<<<NG, 128>>>(hA);
  }

  k_head<<<NG, 64>>>(lin1_w, lin1_b, lin2_w, lin2_b, out);
}

// round 16
// speedup vs baseline: 1.4852x; 1.4852x over previous
#include <cuda_runtime.h>
#include <cuda_fp16.h>
#include <math.h>

#define NN 100000
#define NNP 100096      // 782 * 128
#define NE 800000
#define NG 2048
#define NB 196
#define CAP 160

typedef unsigned int uint;

// ---------------- scratch (device globals; no runtime allocation) ----------------
__device__ __half g_hh[NN*64];              // node features fp16 (ping)
__device__ __half g_hh2[NN*64];             // node features fp16 (pong)
__device__ __half g_Af[(size_t)NNP*320];    // fp16 aggregation panel (pad rows stay zero)
__device__ __half g_Bfh[64*384];            // B^T fp16: [n][k]
__device__ int   g_cnt[NN];
__device__ int   g_rowptr[NN+1];
__device__ int   g_bsum[NB];
__device__ int   g_fill[NN];
__device__ int   g_eidx[NE];                // packed: src | (rel<<20)
__device__ int   g_gstart[NG+1];
__device__ float g_Wl[192*256];
__device__ float g_bl[256];
__device__ float g_s2s[NG*256];             // qstar | hx | cx
__device__ float g_gates[NG*256];

#define G_QS (g_s2s)
#define G_HX (g_s2s + NG*128)
#define G_CX (g_s2s + NG*192)

// ---------------- prep kernels ----------------
__global__ void k_wc(const float* __restrict__ att, const float* __restrict__ basis,
                     const float* __restrict__ root){
  int k = blockIdx.x, e = threadIdx.x;
  float s;
  if (k < 320){
    int r = k >> 6, d = k & 63;
    s = 0.f;
    #pragma unroll
    for (int b = 0; b < 5; b++) s += att[r*5+b] * basis[(b*64+d)*64+e];
  } else {
    s = root[(k-320)*64 + e];
  }
  g_Bfh[e*384 + k] = __float2half_rn(s);
}

// h0 + zero g_cnt (runs before k_hist)
__global__ void __launch_bounds__(256) k_h0(const float* __restrict__ x,
                                            const float* __restrict__ w,
                                            const float* __restrict__ b){
  int gid = blockIdx.x*256 + threadIdx.x;
  if (gid < NN) g_cnt[gid] = 0;
  __shared__ float sx[4][15];
  int tid = threadIdx.x;
  int local = tid >> 6, e = tid & 63;
  int n = blockIdx.x*4 + local;
  if (e < 15 && n < NN) sx[local][e] = x[n*15+e];
  __syncthreads();
  if (n >= NN) return;
  float s = b[e];
  #pragma unroll
  for (int i = 0; i < 15; i++) s += sx[local][i]*w[i*64+e];
  g_hh[(size_t)n*64+e] = __float2half_rn(fmaxf(s, 0.f));
}

__global__ void k_hist(const int* __restrict__ dst){
  int e = blockIdx.x*blockDim.x + threadIdx.x;
  if (e < NE) atomicAdd(&g_cnt[dst[e]], 1);
}

__global__ void k_scan1(){
  __shared__ int sm[512];
  int b = blockIdx.x, t = threadIdx.x;
  int i = b*512 + t;
  sm[t] = (i < NN) ? g_cnt[i] : 0;
  __syncthreads();
  for (int o = 256; o; o >>= 1){
    if (t < o) sm[t] += sm[t+o];
    __syncthreads();
  }
  if (t == 0) g_bsum[b] = sm[0];
}

// merged scan2+scan3 + zero g_fill
__global__ void k_scan23(){
  __shared__ int sm[512];
  __shared__ int sb[256];
  int b = blockIdx.x, t = threadIdx.x;
  if (t < 256) sb[t] = (t < NB) ? g_bsum[t] : 0;
  __syncthreads();
  for (int o = 1; o < 256; o <<= 1){
    int a = (t < 256 && t >= o) ? sb[t-o] : 0;
    __syncthreads();
    if (t < 256) sb[t] += a;
    __syncthreads();
  }
  int off = (b == 0) ? 0 : sb[b-1];
  int i = b*512 + t;
  int v = (i < NN) ? g_cnt[i] : 0;
  sm[t] = v;
  __syncthreads();
  for (int o = 1; o < 512; o <<= 1){
    int add = (t >= o) ? sm[t-o] : 0;
    __syncthreads();
    sm[t] += add;
    __syncthreads();
  }
  if (i < NN){
    g_rowptr[i] = off + sm[t] - v;
    g_fill[i] = 0;
  }
  if (b == 0 && t == 0) g_rowptr[NN] = NE;
}

__global__ void k_scatter(const int* __restrict__ ei, const int* __restrict__ et){
  int e = blockIdx.x*blockDim.x + threadIdx.x;
  if (e >= NE) return;
  int src = ei[e];
  int dst = ei[NE + e];
  int rel = et[e];
  int pos = g_rowptr[dst] + atomicAdd(&g_fill[dst], 1);
  g_eidx[pos] = src | (rel << 20);
}

// LSTM weight pack + graph-offset binary search + s2s state zero
__global__ void k_wl(const float* __restrict__ w_ih, const float* __restrict__ w_hh,
                     const float* __restrict__ b_ih, const float* __restrict__ b_hh,
                     const int* __restrict__ batch){
  int k = blockIdx.x, j = threadIdx.x;
  g_Wl[k*256+j] = (k < 128) ? w_ih[j*128+k] : w_hh[j*64 + (k-128)];
  if (k == 0) g_bl[j] = b_ih[j] + b_hh[j];
  int gt = blockIdx.x*256 + threadIdx.x;
  for (int i = gt; i < NG*256; i += 192*256) g_s2s[i] = 0.f;
  if (gt <= NG){
    int lo = 0, hi = NN;
    while (lo < hi){ int mid = (lo+hi) >> 1; if (batch[mid] < gt) lo = mid+1; else hi = mid; }
    g_gstart[gt] = lo;
  }
}

// ---------------- aggregation: warp-per-node CSR over fp16 h -> fp16 panel ----------------
__global__ void __launch_bounds__(256) k_agg(const __half* __restrict__ hin){
  int n = (blockIdx.x*blockDim.x + threadIdx.x) >> 5;
  int lane = threadIdx.x & 31;
  float ac[5][2] = {};
  int rp0 = g_rowptr[n], rp1 = g_rowptr[n+1];
  int e = rp0;
  for (; e + 2 <= rp1; e += 2){
    int p0 = g_eidx[e], p1 = g_eidx[e+1];
    float2 x = __half22float2(*(const __half2*)(hin + (size_t)(p0 & 0xFFFFF)*64 + 2*lane));
    float2 y = __half22float2(*(const __half2*)(hin + (size_t)(p1 & 0xFFFFF)*64 + 2*lane));
    int r0 = p0 >> 20, r1 = p1 >> 20;
    #pragma unroll
    for (int r = 0; r < 5; r++){
      if (r0 == r){ ac[r][0] += x.x; ac[r][1] += x.y; }
      if (r1 == r){ ac[r][0] += y.x; ac[r][1] += y.y; }
    }
  }
  if (e < rp1){
    int p0 = g_eidx[e];
    float2 x = __half22float2(*(const __half2*)(hin + (size_t)(p0 & 0xFFFFF)*64 + 2*lane));
    int r0 = p0 >> 20;
    #pragma unroll
    for (int r = 0; r < 5; r++)
      if (r0 == r){ ac[r][0] += x.x; ac[r][1] += x.y; }
  }
  float ic = 1.0f / fmaxf((float)(rp1 - rp0), 1.0f);
  size_t base = (size_t)n*320 + 2*lane;
  #pragma unroll
  for (int r = 0; r < 5; r++){
    float2 v = { ac[r][0]*ic, ac[r][1]*ic };
    *(__half2*)(g_Af + base + r*64) = __float22half2_rn(v);
  }
}

// ---------------- GEMM: [NNP x 384] @ [384 x 64] fp16 MMA, 1-term, double-buffered ----------------
#define MMA_F16(d, a, b0v, b1v) \
  asm volatile("mma.sync.aligned.m16n8k16.row.col.f32.f16.f16.f32 " \
      "{%0,%1,%2,%3}, {%4,%5,%6,%7}, {%8,%9}, {%0,%1,%2,%3};" \
      : "+f"(d[0]), "+f"(d[1]), "+f"(d[2]), "+f"(d[3]) \
      : "r"(a[0]), "r"(a[1]), "r"(a[2]), "r"(a[3]), "r"(b0v), "r"(b1v))

__global__ void __launch_bounds__(256) k_gemm(const __half* __restrict__ hin,
                                              __half* __restrict__ hout,
                                              const float* __restrict__ cb){
  __shared__ __half Ah_s[2][128][40];
  __shared__ __half Bh_s[2][64][40];
  int tid = threadIdx.x, lane = tid & 31, w = tid >> 5;
  int m0 = blockIdx.x * 128;
  int wrow = w * 16;
  int r = lane >> 2;            // 0..7
  int q2 = (lane & 3) * 2;      // 0,2,4,6

  float acc[8][4];
  #pragma unroll
  for (int nt = 0; nt < 8; nt++)
    #pragma unroll
    for (int j = 0; j < 4; j++) acc[nt][j] = 0.f;

  int srow = tid >> 1, sseg = (tid & 1) * 16;    // A staging: 16 halves per thread
  int sn = tid >> 2,  sbs = (tid & 3) * 8;       // B staging: 8 halves per thread
  int rw = m0 + srow; if (rw >= NN) rw = NN - 1;
  const __half* hrow = hin + (size_t)rw*64;

  uint4 pf0, pf1, pf2;
  auto LD = [&](int cc){
    const __half* pa = (cc < 10)
        ? g_Af + (size_t)(m0 + srow)*320 + cc*32 + sseg
        : hrow + (cc - 10)*32 + sseg;
    pf0 = *(const uint4*)pa;
    pf1 = *(const uint4*)(pa + 8);
    pf2 = *(const uint4*)(g_Bfh + sn*384 + cc*32 + sbs);
  };
  auto ST = [&](int buf){
    *(uint4*)&Ah_s[buf][srow][sseg]     = pf0;
    *(uint4*)&Ah_s[buf][srow][sseg + 8] = pf1;
    *(uint4*)&Bh_s[buf][sn][sbs] = pf2;
  };

  LD(0); ST(0);
  __syncthreads();

  for (int cc = 0; cc < 12; cc++){
    int buf = cc & 1;
    if (cc < 11) LD(cc + 1);            // global loads in flight during MMA
    #pragma unroll
    for (int s = 0; s < 2; s++){
      int ks = s * 16;
      uint ah[4];
      ah[0] = *(const uint*)&Ah_s[buf][wrow + r    ][ks + q2];
      ah[1] = *(const uint*)&Ah_s[buf][wrow + r + 8][ks + q2];
      ah[2] = *(const uint*)&Ah_s[buf][wrow + r    ][ks + q2 + 8];
      ah[3] = *(const uint*)&Ah_s[buf][wrow + r + 8][ks + q2 + 8];
      #pragma unroll
      for (int nt = 0; nt < 8; nt++){
        int nn = nt*8 + r;
        uint bh0 = *(const uint*)&Bh_s[buf][nn][ks + q2];
        uint bh1 = *(const uint*)&Bh_s[buf][nn][ks + q2 + 8];
        MMA_F16(acc[nt], ah, bh0, bh1);
      }
    }
    if (cc < 11) ST(buf ^ 1);           // write other buffer (readers synced last iter)
    __syncthreads();
  }

  // epilogue: relu(acc + bias) -> fp16 h
  int row0 = m0 + wrow + r;
  #pragma unroll
  for (int nt = 0; nt < 8; nt++){
    int col = nt*8 + q2;
    float b0v = cb[col], b1v = cb[col+1];
    if (row0 < NN){
      *(__half2*)(hout + (size_t)row0*64 + col) =
        __floats2half2_rn(fmaxf(acc[nt][0] + b0v, 0.f), fmaxf(acc[nt][1] + b1v, 0.f));
    }
    if (row0 + 8 < NN){
      *(__half2*)(hout + (size_t)(row0+8)*64 + col) =
        __floats2half2_rn(fmaxf(acc[nt][2] + b0v, 0.f), fmaxf(acc[nt][3] + b1v, 0.f));
    }
  }
}

// ---------------- Set2Set ----------------
__global__ void __launch_bounds__(256) k_gates(){
  __shared__ float Asg[64][36];
  __shared__ float Bsg[32][64];
  int tid = threadIdx.x;
  int tx = tid & 15, ty = tid >> 4;
  int m0 = blockIdx.x * 64;
  int n0 = blockIdx.y * 64;
  int lrow = tid >> 2;
  int lk = (tid & 3) * 8;
  int grow = m0 + lrow;
  int bk = tid >> 3, be = (tid & 7) * 8;
  float acc[4][4] = {};
  for (int kk = 0; kk < 6; kk++){
    int kb = kk * 32;
    float4 a0, a1;
    if (kk < 4){
      const float* p = G_QS + grow*128 + kb + lk;
      a0 = *(const float4*)p; a1 = *(const float4*)(p+4);
    } else {
      const float* p = G_HX + grow*64 + (kb - 128) + lk;
      a0 = *(const float4*)p; a1 = *(const float4*)(p+4);
    }
    const float* wp = g_Wl + (kb + bk)*256 + n0 + be;
    float4 b0 = *(const float4*)wp;
    float4 b1 = *(const float4*)(wp+4);
    __syncthreads();
    *(float4*)&Asg[lrow][lk]   = a0;
    *(float4*)&Asg[lrow][lk+4] = a1;
    *(float4*)&Bsg[bk][be]     = b0;
    *(float4*)&Bsg[bk][be+4]   = b1;
    __syncthreads();
    #pragma unroll
    for (int k = 0; k < 32; k++){
      float4 bv = *(float4*)&Bsg[k][tx*4];
      #pragma unroll
      for (int i = 0; i < 4; i++){
        float av = Asg[ty*4+i][k];
        acc[i][0] += av*bv.x;
        acc[i][1] += av*bv.y;
        acc[i][2] += av*bv.z;
        acc[i][3] += av*bv.w;
      }
    }
  }
  #pragma unroll
  for (int i = 0; i < 4; i++){
    int m = m0 + ty*4 + i;
    float* op = g_gates + m*256 + n0 + tx*4;
    op[0] = acc[i][0] + g_bl[n0 + tx*4 + 0];
    op[1] = acc[i][1] + g_bl[n0 + tx*4 + 1];
    op[2] = acc[i][2] + g_bl[n0 + tx*4 + 2];
    op[3] = acc[i][3] + g_bl[n0 + tx*4 + 3];
  }
}

__device__ __forceinline__ float sigf(float v){ return 1.0f/(1.0f + __expf(-v)); }

// fused LSTM update + softmax readout over fp16 h. Block per graph, 128 threads.
// weighted sum parallelized across 4 warps.
__global__ void __launch_bounds__(128) k_read(const __half* __restrict__ h){
  __shared__ float se[CAP];
  __shared__ float shx[64];
  __shared__ float red[1];
  __shared__ float ps[4];
  __shared__ float2 sr[4][32];
  int g = blockIdx.x;
  int tid = threadIdx.x, lane = tid & 31, w = tid >> 5;
  int s0 = g_gstart[g];
  int cnt = g_gstart[g+1] - s0;
  if (cnt > CAP) cnt = CAP;
  // LSTM update (threads 0..63)
  if (tid < 64){
    const float* ga = g_gates + g*256;
    float iv = sigf(ga[tid]);
    float fv = sigf(ga[64+tid]);
    float gv = tanhf(ga[128+tid]);
    float ov = sigf(ga[192+tid]);
    float c = fv * G_CX[g*64+tid] + iv * gv;
    float hx = ov * tanhf(c);
    G_CX[g*64+tid] = c;
    G_HX[g*64+tid] = hx;
    shx[tid] = hx;
  }
  __syncthreads();
  // e per node
  for (int i = w; i < cnt; i += 4){
    const __half2* hr = (const __half2*)(h + (size_t)(s0+i)*64);
    float2 f = __half22float2(hr[lane]);
    float s = f.x*shx[2*lane] + f.y*shx[2*lane+1];
    #pragma unroll
    for (int o = 16; o; o >>= 1) s += __shfl_xor_sync(0xffffffffu, s, o);
    if (lane == 0) se[i] = s;
  }
  __syncthreads();
  // max
  if (tid < 32){
    float m = -3.0e38f;
    for (int i = lane; i < cnt; i += 32) m = fmaxf(m, se[i]);
    #pragma unroll
    for (int o = 16; o; o >>= 1) m = fmaxf(m, __shfl_xor_sync(0xffffffffu, m, o));
    if (lane == 0) red[0] = m;
  }
  __syncthreads();
  float m = red[0];
  // exp + partial sums
  float psum = 0.f;
  for (int i = tid; i < cnt; i += 128){
    float v = __expf(se[i] - m);
    se[i] = v;
    psum += v;
  }
  #pragma unroll
  for (int o = 16; o; o >>= 1) psum += __shfl_xor_sync(0xffffffffu, psum, o);
  if (lane == 0) ps[w] = psum;
  __syncthreads();
  float ssum = ps[0] + ps[1] + ps[2] + ps[3];
  // weighted sum: warp w handles nodes i = w, w+4, ... ; lane -> dim pair
  {
    float r0 = 0.f, r1 = 0.f;
    for (int i = w; i < cnt; i += 4){
      float a = se[i];
      const __half2* hr = (const __half2*)(h + (size_t)(s0+i)*64);
      float2 f = __half22float2(hr[lane]);
      r0 += a * f.x;
      r1 += a * f.y;
    }
    sr[w][lane] = make_float2(r0, r1);
  }
  __syncthreads();
  if (tid < 64){
    int pair = tid >> 1, comp = tid & 1;
    float r = 0.f;
    #pragma unroll
    for (int ww = 0; ww < 4; ww++){
      float2 v = sr[ww][pair];
      r += comp ? v.y : v.x;
    }
    G_QS[g*128 + tid]      = shx[tid];
    G_QS[g*128 + 64 + tid] = (ssum > 0.f) ? (r / ssum) : 0.f;
  }
}

// ---------------- fused head ----------------
__global__ void __launch_bounds__(64) k_head(const float* __restrict__ w1,
                                             const float* __restrict__ b1,
                                             const float* __restrict__ w2,
                                             const float* __restrict__ b2,
                                             float* __restrict__ out){
  __shared__ float so[64];
  int g = blockIdx.x, e = threadIdx.x;
  const float* q = G_QS + g*128;
  float s = b1[e];
  #pragma unroll 8
  for (int k = 0; k < 128; k++) s += q[k]*w1[k*64+e];
  so[e] = fmaxf(s, 0.f);
  __syncthreads();
  if (e < 12){
    float s2 = b2[e];
    #pragma unroll 8
    for (int d = 0; d < 64; d++) s2 += so[d]*w2[d*12+e];
    out[g*12 + e] = s2;
  }
}

// ---------------- launch ----------------
extern "C" void kernel_launch(void* const* d_in, const int* in_sizes, int n_in,
                              void* d_out, int out_size){
  const float* x      = (const float*)d_in[0];
  const int*   ei     = (const int*)  d_in[1];
  const int*   et     = (const int*)  d_in[2];
  const int*   batch  = (const int*)  d_in[3];
  const float* lin0_w = (const float*)d_in[4];
  const float* lin0_b = (const float*)d_in[5];
  const float* basis  = (const float*)d_in[6];
  const float* att    = (const float*)d_in[7];
  const float* root   = (const float*)d_in[8];
  const float* conv_b = (const float*)d_in[9];
  const float* w_ih   = (const float*)d_in[10];
  const float* w_hh   = (const float*)d_in[11];
  const float* b_ih   = (const float*)d_in[12];
  const float* b_hh   = (const float*)d_in[13];
  const float* lin1_w = (const float*)d_in[14];
  const float* lin1_b = (const float*)d_in[15];
  const float* lin2_w = (const float*)d_in[16];
  const float* lin2_b = (const float*)d_in[17];
  float* out = (float*)d_out;

  void *p_h=0, *p_h2=0;
  cudaGetSymbolAddress(&p_h,  g_hh);
  cudaGetSymbolAddress(&p_h2, g_hh2);

  // prologue (7 kernels, single stream)
  k_wc<<<384, 64>>>(att, basis, root);
  k_h0<<<(NN+3)/4, 256>>>(x, lin0_w, lin0_b);
  k_hist<<<(NE+255)/256, 256>>>(ei + NE);
  k_scan1<<<NB, 512>>>();
  k_scan23<<<NB, 512>>>();
  k_scatter<<<(NE+255)/256, 256>>>(ei, et);
  k_wl<<<192, 256>>>(w_ih, w_hh, b_ih, b_hh, batch);

  // RGCN propagation: CSR aggregate -> fp16 panel -> 1-term fp16 tensor GEMM
  __half* hA = (__half*)p_h;
  __half* hB = (__half*)p_h2;
  for (int s = 0; s < 6; s++){
    k_agg<<<NN/8, 256>>>(hA);
    k_gemm<<<NNP/128, 256>>>(hA, hB, conv_b);
    __half* tmp = hA; hA = hB; hB = tmp;
  }

  // Set2Set
  for (int t = 0; t < 6; t++){
    k_gates<<<dim3(NG/64, 4), 256>>>();
    k_read<<<NG, 128>>>(hA);
  }

  k_head<<<NG, 64>>>(lin1_w, lin1_b, lin2_w, lin2_b, out);
}

// round 17
// speedup vs baseline: 1.5209x; 1.0240x over previous
#include <cuda_runtime.h>
#include <cuda_fp16.h>
#include <math.h>

#define NN 100000
#define NNP 100096      // 782 * 128
#define NE 800000
#define NG 2048
#define NB 196
#define CAP 160

typedef unsigned int uint;

// ---------------- scratch (device globals; no runtime allocation) ----------------
__device__ __half g_hh[NN*64];              // node features fp16 (ping)
__device__ __half g_hh2[NN*64];             // node features fp16 (pong)
__device__ __half g_Af[(size_t)NNP*320];    // fp16 aggregation panel (pad rows stay zero)
__device__ __half g_Bfh[64*384];            // B^T fp16: [n][k]
__device__ int   g_cnt[NN];
__device__ int   g_rowptr[NN+1];
__device__ int   g_bsum[NB];
__device__ int   g_fill[NN];
__device__ int   g_eidx[NE];                // packed: src | (rel<<20)
__device__ int   g_gstart[NG+1];
__device__ float g_Wl[192*256];
__device__ float g_bl[256];
__device__ float g_s2s[NG*256];             // qstar | hx | cx
__device__ float g_gates[NG*256];

#define G_QS (g_s2s)
#define G_HX (g_s2s + NG*128)
#define G_CX (g_s2s + NG*192)

// ---------------- merged weight prep: Bfh (blocks 0..95) + Wl/gstart/s2s-zero (96..287) ----------------
__global__ void __launch_bounds__(256) k_prep(const float* __restrict__ att,
                                              const float* __restrict__ basis,
                                              const float* __restrict__ root,
                                              const float* __restrict__ w_ih,
                                              const float* __restrict__ w_hh,
                                              const float* __restrict__ b_ih,
                                              const float* __restrict__ b_hh,
                                              const int* __restrict__ batch){
  int b = blockIdx.x, tid = threadIdx.x;
  if (b < 96){
    int k = b*4 + (tid >> 6);
    int e = tid & 63;
    float s;
    if (k < 320){
      int r = k >> 6, d = k & 63;
      s = 0.f;
      #pragma unroll
      for (int bb = 0; bb < 5; bb++) s += att[r*5+bb] * basis[(bb*64+d)*64+e];
    } else {
      s = root[(k-320)*64 + e];
    }
    g_Bfh[e*384 + k] = __float2half_rn(s);
  } else {
    int k = b - 96;          // 0..191
    int j = tid;
    g_Wl[k*256+j] = (k < 128) ? w_ih[j*128+k] : w_hh[j*64 + (k-128)];
    if (k == 0) g_bl[j] = b_ih[j] + b_hh[j];
    int gt = k*256 + tid;
    for (int i = gt; i < NG*256; i += 192*256) g_s2s[i] = 0.f;
    if (gt <= NG){
      int lo = 0, hi = NN;
      while (lo < hi){ int mid = (lo+hi) >> 1; if (batch[mid] < gt) lo = mid+1; else hi = mid; }
      g_gstart[gt] = lo;
    }
  }
}

// h0 + zero g_cnt (runs before k_hist)
__global__ void __launch_bounds__(256) k_h0(const float* __restrict__ x,
                                            const float* __restrict__ w,
                                            const float* __restrict__ b){
  int gid = blockIdx.x*256 + threadIdx.x;
  if (gid < NN) g_cnt[gid] = 0;
  __shared__ float sx[4][15];
  int tid = threadIdx.x;
  int local = tid >> 6, e = tid & 63;
  int n = blockIdx.x*4 + local;
  if (e < 15 && n < NN) sx[local][e] = x[n*15+e];
  __syncthreads();
  if (n >= NN) return;
  float s = b[e];
  #pragma unroll
  for (int i = 0; i < 15; i++) s += sx[local][i]*w[i*64+e];
  g_hh[(size_t)n*64+e] = __float2half_rn(fmaxf(s, 0.f));
}

__global__ void k_hist(const int* __restrict__ dst){
  int e = blockIdx.x*blockDim.x + threadIdx.x;
  if (e < NE) atomicAdd(&g_cnt[dst[e]], 1);
}

__global__ void k_scan1(){
  __shared__ int sm[512];
  int b = blockIdx.x, t = threadIdx.x;
  int i = b*512 + t;
  sm[t] = (i < NN) ? g_cnt[i] : 0;
  __syncthreads();
  for (int o = 256; o; o >>= 1){
    if (t < o) sm[t] += sm[t+o];
    __syncthreads();
  }
  if (t == 0) g_bsum[b] = sm[0];
}

// merged scan2+scan3 + zero g_fill
__global__ void k_scan23(){
  __shared__ int sm[512];
  __shared__ int sb[256];
  int b = blockIdx.x, t = threadIdx.x;
  if (t < 256) sb[t] = (t < NB) ? g_bsum[t] : 0;
  __syncthreads();
  for (int o = 1; o < 256; o <<= 1){
    int a = (t < 256 && t >= o) ? sb[t-o] : 0;
    __syncthreads();
    if (t < 256) sb[t] += a;
    __syncthreads();
  }
  int off = (b == 0) ? 0 : sb[b-1];
  int i = b*512 + t;
  int v = (i < NN) ? g_cnt[i] : 0;
  sm[t] = v;
  __syncthreads();
  for (int o = 1; o < 512; o <<= 1){
    int add = (t >= o) ? sm[t-o] : 0;
    __syncthreads();
    sm[t] += add;
    __syncthreads();
  }
  if (i < NN){
    g_rowptr[i] = off + sm[t] - v;
    g_fill[i] = 0;
  }
  if (b == 0 && t == 0) g_rowptr[NN] = NE;
}

__global__ void k_scatter(const int* __restrict__ ei, const int* __restrict__ et){
  int e = blockIdx.x*blockDim.x + threadIdx.x;
  if (e >= NE) return;
  int src = ei[e];
  int dst = ei[NE + e];
  int rel = et[e];
  int pos = g_rowptr[dst] + atomicAdd(&g_fill[dst], 1);
  g_eidx[pos] = src | (rel << 20);
}

// ---------------- aggregation: warp-per-node CSR over fp16 h -> fp16 panel ----------------
__global__ void __launch_bounds__(256) k_agg(const __half* __restrict__ hin){
  int n = (blockIdx.x*blockDim.x + threadIdx.x) >> 5;
  int lane = threadIdx.x & 31;
  float ac[5][2] = {};
  int rp0 = g_rowptr[n], rp1 = g_rowptr[n+1];
  int e = rp0;
  for (; e + 2 <= rp1; e += 2){
    int p0 = g_eidx[e], p1 = g_eidx[e+1];
    float2 x = __half22float2(*(const __half2*)(hin + (size_t)(p0 & 0xFFFFF)*64 + 2*lane));
    float2 y = __half22float2(*(const __half2*)(hin + (size_t)(p1 & 0xFFFFF)*64 + 2*lane));
    int r0 = p0 >> 20, r1 = p1 >> 20;
    #pragma unroll
    for (int r = 0; r < 5; r++){
      if (r0 == r){ ac[r][0] += x.x; ac[r][1] += x.y; }
      if (r1 == r){ ac[r][0] += y.x; ac[r][1] += y.y; }
    }
  }
  if (e < rp1){
    int p0 = g_eidx[e];
    float2 x = __half22float2(*(const __half2*)(hin + (size_t)(p0 & 0xFFFFF)*64 + 2*lane));
    int r0 = p0 >> 20;
    #pragma unroll
    for (int r = 0; r < 5; r++)
      if (r0 == r){ ac[r][0] += x.x; ac[r][1] += x.y; }
  }
  float ic = 1.0f / fmaxf((float)(rp1 - rp0), 1.0f);
  size_t base = (size_t)n*320 + 2*lane;
  #pragma unroll
  for (int r = 0; r < 5; r++){
    float2 v = { ac[r][0]*ic, ac[r][1]*ic };
    *(__half2*)(g_Af + base + r*64) = __float22half2_rn(v);
  }
}

// ---------------- GEMM: [NNP x 384] @ [384 x 64] fp16 MMA, 1-term, double-buffered ----------------
#define MMA_F16(d, a, b0v, b1v) \
  asm volatile("mma.sync.aligned.m16n8k16.row.col.f32.f16.f16.f32 " \
      "{%0,%1,%2,%3}, {%4,%5,%6,%7}, {%8,%9}, {%0,%1,%2,%3};" \
      : "+f"(d[0]), "+f"(d[1]), "+f"(d[2]), "+f"(d[3]) \
      : "r"(a[0]), "r"(a[1]), "r"(a[2]), "r"(a[3]), "r"(b0v), "r"(b1v))

__global__ void __launch_bounds__(256) k_gemm(const __half* __restrict__ hin,
                                              __half* __restrict__ hout,
                                              const float* __restrict__ cb){
  __shared__ __half Ah_s[2][128][40];
  __shared__ __half Bh_s[2][64][40];
  int tid = threadIdx.x, lane = tid & 31, w = tid >> 5;
  int m0 = blockIdx.x * 128;
  int wrow = w * 16;
  int r = lane >> 2;            // 0..7
  int q2 = (lane & 3) * 2;      // 0,2,4,6

  float acc[8][4];
  #pragma unroll
  for (int nt = 0; nt < 8; nt++)
    #pragma unroll
    for (int j = 0; j < 4; j++) acc[nt][j] = 0.f;

  int srow = tid >> 1, sseg = (tid & 1) * 16;    // A staging: 16 halves per thread
  int sn = tid >> 2,  sbs = (tid & 3) * 8;       // B staging: 8 halves per thread
  int rw = m0 + srow; if (rw >= NN) rw = NN - 1;
  const __half* hrow = hin + (size_t)rw*64;

  uint4 pf0, pf1, pf2;
  auto LD = [&](int cc){
    const __half* pa = (cc < 10)
        ? g_Af + (size_t)(m0 + srow)*320 + cc*32 + sseg
        : hrow + (cc - 10)*32 + sseg;
    pf0 = *(const uint4*)pa;
    pf1 = *(const uint4*)(pa + 8);
    pf2 = *(const uint4*)(g_Bfh + sn*384 + cc*32 + sbs);
  };
  auto ST = [&](int buf){
    *(uint4*)&Ah_s[buf][srow][sseg]     = pf0;
    *(uint4*)&Ah_s[buf][srow][sseg + 8] = pf1;
    *(uint4*)&Bh_s[buf][sn][sbs] = pf2;
  };

  LD(0); ST(0);
  __syncthreads();

  for (int cc = 0; cc < 12; cc++){
    int buf = cc & 1;
    if (cc < 11) LD(cc + 1);            // global loads in flight during MMA
    #pragma unroll
    for (int s = 0; s < 2; s++){
      int ks = s * 16;
      uint ah[4];
      ah[0] = *(const uint*)&Ah_s[buf][wrow + r    ][ks + q2];
      ah[1] = *(const uint*)&Ah_s[buf][wrow + r + 8][ks + q2];
      ah[2] = *(const uint*)&Ah_s[buf][wrow + r    ][ks + q2 + 8];
      ah[3] = *(const uint*)&Ah_s[buf][wrow + r + 8][ks + q2 + 8];
      #pragma unroll
      for (int nt = 0; nt < 8; nt++){
        int nn = nt*8 + r;
        uint bh0 = *(const uint*)&Bh_s[buf][nn][ks + q2];
        uint bh1 = *(const uint*)&Bh_s[buf][nn][ks + q2 + 8];
        MMA_F16(acc[nt], ah, bh0, bh1);
      }
    }
    if (cc < 11) ST(buf ^ 1);           // write other buffer (readers synced last iter)
    __syncthreads();
  }

  // epilogue: relu(acc + bias) -> fp16 h
  int row0 = m0 + wrow + r;
  #pragma unroll
  for (int nt = 0; nt < 8; nt++){
    int col = nt*8 + q2;
    float b0v = cb[col], b1v = cb[col+1];
    if (row0 < NN){
      *(__half2*)(hout + (size_t)row0*64 + col) =
        __floats2half2_rn(fmaxf(acc[nt][0] + b0v, 0.f), fmaxf(acc[nt][1] + b1v, 0.f));
    }
    if (row0 + 8 < NN){
      *(__half2*)(hout + (size_t)(row0+8)*64 + col) =
        __floats2half2_rn(fmaxf(acc[nt][2] + b0v, 0.f), fmaxf(acc[nt][3] + b1v, 0.f));
    }
  }
}

// ---------------- Set2Set gates GEMM ----------------
__global__ void __launch_bounds__(256) k_gates(){
  __shared__ float Asg[64][36];
  __shared__ float Bsg[32][64];
  int tid = threadIdx.x;
  int tx = tid & 15, ty = tid >> 4;
  int m0 = blockIdx.x * 64;
  int n0 = blockIdx.y * 64;
  int lrow = tid >> 2;
  int lk = (tid & 3) * 8;
  int grow = m0 + lrow;
  int bk = tid >> 3, be = (tid & 7) * 8;
  float acc[4][4] = {};
  for (int kk = 0; kk < 6; kk++){
    int kb = kk * 32;
    float4 a0, a1;
    if (kk < 4){
      const float* p = G_QS + grow*128 + kb + lk;
      a0 = *(const float4*)p; a1 = *(const float4*)(p+4);
    } else {
      const float* p = G_HX + grow*64 + (kb - 128) + lk;
      a0 = *(const float4*)p; a1 = *(const float4*)(p+4);
    }
    const float* wp = g_Wl + (kb + bk)*256 + n0 + be;
    float4 b0 = *(const float4*)wp;
    float4 b1 = *(const float4*)(wp+4);
    __syncthreads();
    *(float4*)&Asg[lrow][lk]   = a0;
    *(float4*)&Asg[lrow][lk+4] = a1;
    *(float4*)&Bsg[bk][be]     = b0;
    *(float4*)&Bsg[bk][be+4]   = b1;
    __syncthreads();
    #pragma unroll
    for (int k = 0; k < 32; k++){
      float4 bv = *(float4*)&Bsg[k][tx*4];
      #pragma unroll
      for (int i = 0; i < 4; i++){
        float av = Asg[ty*4+i][k];
        acc[i][0] += av*bv.x;
        acc[i][1] += av*bv.y;
        acc[i][2] += av*bv.z;
        acc[i][3] += av*bv.w;
      }
    }
  }
  #pragma unroll
  for (int i = 0; i < 4; i++){
    int m = m0 + ty*4 + i;
    float* op = g_gates + m*256 + n0 + tx*4;
    op[0] = acc[i][0] + g_bl[n0 + tx*4 + 0];
    op[1] = acc[i][1] + g_bl[n0 + tx*4 + 1];
    op[2] = acc[i][2] + g_bl[n0 + tx*4 + 2];
    op[3] = acc[i][3] + g_bl[n0 + tx*4 + 3];
  }
}

__device__ __forceinline__ float sigf(float v){ return 1.0f/(1.0f + __expf(-v)); }

// fused LSTM update + softmax readout (+ optional final head). Block per graph, 128 threads.
// t0: gates come analytically from g_bl (qstar=hx=0). doh: run MLP head at the end.
__global__ void __launch_bounds__(128) k_read(const __half* __restrict__ h,
                                              int t0, int doh,
                                              const float* __restrict__ w1,
                                              const float* __restrict__ b1,
                                              const float* __restrict__ w2,
                                              const float* __restrict__ b2,
                                              float* __restrict__ out){
  __shared__ float se[CAP];
  __shared__ float sq[128];
  __shared__ float red[1];
  __shared__ float ps[4];
  __shared__ float2 sr[4][32];
  int g = blockIdx.x;
  int tid = threadIdx.x, lane = tid & 31, w = tid >> 5;
  int s0 = g_gstart[g];
  int cnt = g_gstart[g+1] - s0;
  if (cnt > CAP) cnt = CAP;
  // LSTM update (threads 0..63)
  if (tid < 64){
    const float* ga = t0 ? g_bl : (g_gates + g*256);
    float iv = sigf(ga[tid]);
    float fv = sigf(ga[64+tid]);
    float gv = tanhf(ga[128+tid]);
    float ov = sigf(ga[192+tid]);
    float c = fv * G_CX[g*64+tid] + iv * gv;
    float hx = ov * tanhf(c);
    G_CX[g*64+tid] = c;
    G_HX[g*64+tid] = hx;
    sq[tid] = hx;
  }
  __syncthreads();
  // e per node
  for (int i = w; i < cnt; i += 4){
    const __half2* hr = (const __half2*)(h + (size_t)(s0+i)*64);
    float2 f = __half22float2(hr[lane]);
    float s = f.x*sq[2*lane] + f.y*sq[2*lane+1];
    #pragma unroll
    for (int o = 16; o; o >>= 1) s += __shfl_xor_sync(0xffffffffu, s, o);
    if (lane == 0) se[i] = s;
  }
  __syncthreads();
  // max
  if (tid < 32){
    float m = -3.0e38f;
    for (int i = lane; i < cnt; i += 32) m = fmaxf(m, se[i]);
    #pragma unroll
    for (int o = 16; o; o >>= 1) m = fmaxf(m, __shfl_xor_sync(0xffffffffu, m, o));
    if (lane == 0) red[0] = m;
  }
  __syncthreads();
  float m = red[0];
  // exp + partial sums
  float psum = 0.f;
  for (int i = tid; i < cnt; i += 128){
    float v = __expf(se[i] - m);
    se[i] = v;
    psum += v;
  }
  #pragma unroll
  for (int o = 16; o; o >>= 1) psum += __shfl_xor_sync(0xffffffffu, psum, o);
  if (lane == 0) ps[w] = psum;
  __syncthreads();
  float ssum = ps[0] + ps[1] + ps[2] + ps[3];
  // weighted sum: warp w handles nodes i = w, w+4, ... ; lane -> dim pair
  {
    float r0 = 0.f, r1 = 0.f;
    for (int i = w; i < cnt; i += 4){
      float a = se[i];
      const __half2* hr = (const __half2*)(h + (size_t)(s0+i)*64);
      float2 f = __half22float2(hr[lane]);
      r0 += a * f.x;
      r1 += a * f.y;
    }
    sr[w][lane] = make_float2(r0, r1);
  }
  __syncthreads();
  if (tid < 64){
    int pair = tid >> 1, comp = tid & 1;
    float r = 0.f;
    #pragma unroll
    for (int ww = 0; ww < 4; ww++){
      float2 v = sr[ww][pair];
      r += comp ? v.y : v.x;
    }
    float rv = (ssum > 0.f) ? (r / ssum) : 0.f;
    G_QS[g*128 + tid]      = sq[tid];
    G_QS[g*128 + 64 + tid] = rv;
    sq[64 + tid] = rv;
  }
  // optional fused head (final iteration)
  if (doh){
    __syncthreads();
    __shared__ float so[64];
    if (tid < 64){
      float s = b1[tid];
      #pragma unroll 8
      for (int k = 0; k < 128; k++) s += sq[k]*w1[k*64+tid];
      so[tid] = fmaxf(s, 0.f);
    }
    __syncthreads();
    if (tid < 12){
      float s2 = b2[tid];
      #pragma unroll 8
      for (int d = 0; d < 64; d++) s2 += so[d]*w2[d*12+tid];
      out[g*12 + tid] = s2;
    }
  }
}

// ---------------- launch ----------------
extern "C" void kernel_launch(void* const* d_in, const int* in_sizes, int n_in,
                              void* d_out, int out_size){
  const float* x      = (const float*)d_in[0];
  const int*   ei     = (const int*)  d_in[1];
  const int*   et     = (const int*)  d_in[2];
  const int*   batch  = (const int*)  d_in[3];
  const float* lin0_w = (const float*)d_in[4];
  const float* lin0_b = (const float*)d_in[5];
  const float* basis  = (const float*)d_in[6];
  const float* att    = (const float*)d_in[7];
  const float* root   = (const float*)d_in[8];
  const float* conv_b = (const float*)d_in[9];
  const float* w_ih   = (const float*)d_in[10];
  const float* w_hh   = (const float*)d_in[11];
  const float* b_ih   = (const float*)d_in[12];
  const float* b_hh   = (const float*)d_in[13];
  const float* lin1_w = (const float*)d_in[14];
  const float* lin1_b = (const float*)d_in[15];
  const float* lin2_w = (const float*)d_in[16];
  const float* lin2_b = (const float*)d_in[17];
  float* out = (float*)d_out;

  void *p_h=0, *p_h2=0;
  cudaGetSymbolAddress(&p_h,  g_hh);
  cudaGetSymbolAddress(&p_h2, g_hh2);

  // prologue (6 kernels, single stream)
  k_h0<<<(NN+3)/4, 256>>>(x, lin0_w, lin0_b);
  k_hist<<<(NE+255)/256, 256>>>(ei + NE);
  k_scan1<<<NB, 512>>>();
  k_scan23<<<NB, 512>>>();
  k_scatter<<<(NE+255)/256, 256>>>(ei, et);
  k_prep<<<288, 256>>>(att, basis, root, w_ih, w_hh, b_ih, b_hh, batch);

  // RGCN propagation: CSR aggregate -> fp16 panel -> 1-term fp16 tensor GEMM
  __half* hA = (__half*)p_h;
  __half* hB = (__half*)p_h2;
  for (int s = 0; s < 6; s++){
    k_agg<<<NN/8, 256>>>(hA);
    k_gemm<<<NNP/128, 256>>>(hA, hB, conv_b);
    __half* tmp = hA; hA = hB; hB = tmp;
  }

  // Set2Set: t=0 gates are analytic (bl); final k_read also runs the head
  k_read<<<NG, 128>>>(hA, 1, 0, lin1_w, lin1_b, lin2_w, lin2_b, out);
  for (int t = 1; t < 6; t++){
    k_gates<<<dim3(NG/64, 4), 256>>>();
    k_read<<<NG, 128>>>(hA, 0, (t == 5) ? 1 : 0, lin1_w, lin1_b, lin2_w, lin2_b, out);
  }
}